// round 1
// baseline (speedup 1.0000x reference)
#include <cuda_runtime.h>

#define NB   32768
#define NCO  64
#define NDG  2048
#define NCA  256
#define KACT 81
#define MR   16
#define NTHR 256
#define STR  20   // padded stride for [256][16] transposed tiles (float4-aligned, 4-way max bank conflict)

// ---------------- device-global scratch (allowed; no runtime allocation) ----------------
__device__ float g_WppT[NCO*NDG];
__device__ float g_WmossyT[NDG*NCA];
__device__ float g_WrecT[NCA*NCA];
__device__ float g_WscT[NCA*NCA];
__device__ float g_WcsT[NCA*NCA];
__device__ float g_WcdT[NCA*NCA];
__device__ float g_WogT[NCA*NCA];
__device__ float g_WtaT[NCO*NCA];
__device__ float g_bufadd[NCO];
__device__ float g_part[256*NCO];

// order-preserving float->uint key
__device__ __forceinline__ unsigned f2u(float f){
    unsigned u = __float_as_uint(f);
    return u ^ ((u & 0x80000000u) ? 0xFFFFFFFFu : 0x80000000u);
}

__device__ __forceinline__ void fma16(float acc[16], const float* __restrict__ sT, float wv){
    const float4* e = (const float4*)sT;
    float4 a=e[0], b=e[1], c=e[2], d=e[3];
    acc[0]=fmaf(a.x,wv,acc[0]);  acc[1]=fmaf(a.y,wv,acc[1]);  acc[2]=fmaf(a.z,wv,acc[2]);  acc[3]=fmaf(a.w,wv,acc[3]);
    acc[4]=fmaf(b.x,wv,acc[4]);  acc[5]=fmaf(b.y,wv,acc[5]);  acc[6]=fmaf(b.z,wv,acc[6]);  acc[7]=fmaf(b.w,wv,acc[7]);
    acc[8]=fmaf(c.x,wv,acc[8]);  acc[9]=fmaf(c.y,wv,acc[9]);  acc[10]=fmaf(c.z,wv,acc[10]); acc[11]=fmaf(c.w,wv,acc[11]);
    acc[12]=fmaf(d.x,wv,acc[12]); acc[13]=fmaf(d.y,wv,acc[13]); acc[14]=fmaf(d.z,wv,acc[14]); acc[15]=fmaf(d.w,wv,acc[15]);
}

// ---------------- column-sum of coords (deterministic 2-stage) ----------------
__global__ void colsum_kernel(const float* __restrict__ coords){
    __shared__ float s[4][64];
    int tid = threadIdx.x;
    int c = tid & 63, g = tid >> 6;
    int r0 = blockIdx.x * 128 + g * 32;
    float acc = 0.f;
    #pragma unroll 8
    for (int i = 0; i < 32; ++i) acc += coords[(r0 + i) * 64 + c];
    s[g][c] = acc;
    __syncthreads();
    if (g == 0) g_part[blockIdx.x * 64 + c] = s[0][c] + s[1][c] + s[2][c] + s[3][c];
}

__global__ void bufred_kernel(){
    int c = threadIdx.x;
    float acc = 0.f;
    for (int b = 0; b < 256; ++b) acc += g_part[b * 64 + c];
    // ec input adds 0.1 * buf, buf = (1-EC_TAU)*mean = 0.5*mean  ->  + 0.05 * mean
    g_bufadd[c] = 0.05f * acc / (float)NB;
}

// ---------------- tiled transpose into selected device-global ----------------
__global__ void transpose_sel(const float* __restrict__ src, int rows, int cols, int sel){
    __shared__ float tile[32][33];
    float* dst;
    switch (sel){
        case 0: dst = g_WppT;    break;
        case 1: dst = g_WmossyT; break;
        case 2: dst = g_WrecT;   break;
        case 3: dst = g_WscT;    break;
        case 4: dst = g_WcsT;    break;
        case 5: dst = g_WcdT;    break;
        case 6: dst = g_WogT;    break;
        default: dst = g_WtaT;   break;
    }
    int bx = blockIdx.x * 32, by = blockIdx.y * 32;
    int tx = threadIdx.x, ty = threadIdx.y;           // 32 x 8
    #pragma unroll
    for (int i = 0; i < 32; i += 8)
        tile[ty + i][tx] = src[(by + ty + i) * cols + (bx + tx)];
    __syncthreads();
    #pragma unroll
    for (int i = 0; i < 32; i += 8)
        dst[(bx + ty + i) * rows + (by + tx)] = tile[tx][ty + i];
}

// ---------------- the fused pipeline: 16 rows per block ----------------
extern "C" __global__ void __launch_bounds__(NTHR, 1)
fused_kernel(const float* __restrict__ coords,
             const float* __restrict__ ec_g,  const float* __restrict__ ec_b,
             const float* __restrict__ b_pp,
             const float* __restrict__ dg_g,  const float* __restrict__ dg_b,
             const float* __restrict__ b_sc,  const float* __restrict__ b_ta,
             const float* __restrict__ b_og,
             float* __restrict__ out)
{
    extern __shared__ float sm[];
    float*    pool   = sm;                       // 32768 f : proj[16][2048], later 4 x [256][STR] buffers
    float*    s_ecT  = sm + 32768;               // 1024  f : ec transposed [64][16]
    float*    s_cueT = s_ecT + 1024;             // 5120  f : cue transposed [256][STR]
    unsigned* s_hist = (unsigned*)(s_cueT + 5120);   // 8 warps x 256 bins
    int*      s_aidx = (int*)(s_hist + 8*256);       // 16 x 84
    float*    s_aval = (float*)(s_aidx + MR*84);     // 16 x 84
    float*    s_nov  = s_aval + MR*84;               // 16

    float* bufA = pool;
    float* bufB = pool + 5120;
    float* bufC = pool + 10240;
    float* bufD = pool + 15360;

    const int tid  = threadIdx.x;
    const int w    = tid >> 5;
    const int lane = tid & 31;
    const unsigned lmask = (1u << lane) - 1u;
    const int row0 = blockIdx.x * MR;

    // ---- Stage 1: EC layernorm (warp handles 2 rows) ----
    for (int rr = 0; rr < 2; ++rr){
        int r  = w * 2 + rr;
        int gr = row0 + r;
        float v1 = coords[gr*64 + lane]      + g_bufadd[lane];
        float v2 = coords[gr*64 + lane + 32] + g_bufadd[lane + 32];
        float s = v1 + v2, s2 = v1*v1 + v2*v2;
        #pragma unroll
        for (int o = 16; o; o >>= 1){ s += __shfl_xor_sync(~0u, s, o); s2 += __shfl_xor_sync(~0u, s2, o); }
        float mu = s * (1.f/64.f);
        float rs = rsqrtf(s2 * (1.f/64.f) - mu*mu + 1e-5f);
        s_ecT[lane*16 + r]      = (v1 - mu) * rs * ec_g[lane]      + ec_b[lane];
        s_ecT[(lane+32)*16 + r] = (v2 - mu) * rs * ec_g[lane + 32] + ec_b[lane + 32];
    }
    __syncthreads();

    // ---- Stage 2: proj = relu(ec @ WppT + b_pp)  -> pool[16][2048] ----
    for (int nt = 0; nt < 8; ++nt){
        int c = nt * 256 + tid;
        float acc[16];
        float bp = b_pp[c];
        #pragma unroll
        for (int r = 0; r < 16; ++r) acc[r] = bp;
        #pragma unroll 4
        for (int k = 0; k < 64; ++k){
            float wv = g_WppT[k*NDG + c];
            fma16(acc, s_ecT + k*16, wv);
        }
        #pragma unroll
        for (int r = 0; r < 16; ++r) pool[r*NDG + c] = fmaxf(acc[r], 0.f);
    }
    __syncthreads();

    // ---- Stage 3+4 per warp: DG layernorm + exact top-81 radix select + compaction ----
    unsigned* hist = s_hist + w * 256;
    for (int rr = 0; rr < 2; ++rr){
        int r = w * 2 + rr;
        float* row = pool + r * NDG;
        float s = 0.f, s2 = 0.f;
        for (int i = lane; i < NDG; i += 32){ float v = row[i]; s += v; s2 += v*v; }
        #pragma unroll
        for (int o = 16; o; o >>= 1){ s += __shfl_xor_sync(~0u, s, o); s2 += __shfl_xor_sync(~0u, s2, o); }
        float mu = s * (1.f/2048.f);
        float rs = rsqrtf(s2 * (1.f/2048.f) - mu*mu + 1e-5f);
        for (int i = lane; i < NDG; i += 32)
            row[i] = (row[i] - mu) * rs * dg_g[i] + dg_b[i];
        __syncwarp();

        // exact K-th largest via byte radix select on order-preserving key
        unsigned prefix = 0; int need = KACT;
        for (int p = 3; p >= 0; --p){
            for (int b = lane; b < 256; b += 32) hist[b] = 0;
            __syncwarp();
            unsigned himask = (p == 3) ? 0u : (0xFFFFFFFFu << ((p + 1) * 8));
            for (int i = lane; i < NDG; i += 32){
                unsigned u = f2u(row[i]);
                if ((u & himask) == prefix) atomicAdd(&hist[(u >> (p*8)) & 255], 1u);
            }
            __syncwarp();
            int b0 = 255 - lane * 8;
            unsigned cs[8]; unsigned cnt = 0;
            #pragma unroll
            for (int t = 0; t < 8; ++t){ cs[t] = hist[b0 - t]; cnt += cs[t]; }
            unsigned inc = cnt;
            #pragma unroll
            for (int o = 1; o < 32; o <<= 1){ unsigned v = __shfl_up_sync(~0u, inc, o); if (lane >= o) inc += v; }
            unsigned excl = inc - cnt;
            bool hit = (excl < (unsigned)need) && ((unsigned)need <= inc);
            unsigned bal = __ballot_sync(~0u, hit);
            int srcl = __ffs(bal) - 1;
            int selbin = 0, newneed = 0, found = 0;
            if (hit){
                unsigned cum = excl;
                #pragma unroll
                for (int t = 0; t < 8; ++t){
                    unsigned nc = cum + cs[t];
                    if (!found && nc >= (unsigned)need){ selbin = b0 - t; newneed = need - (int)cum; found = 1; }
                    cum = nc;
                }
            }
            selbin = __shfl_sync(~0u, selbin, srcl);
            need   = __shfl_sync(~0u, newneed, srcl);
            prefix |= ((unsigned)selbin) << (p * 8);
        }

        // compact actives (all keys > T, plus first `need` == T in ascending index order)
        int base = 0, ties = 0;
        for (int g = 0; g < 64; ++g){
            int c = g * 32 + lane;
            float v = row[c];
            unsigned u = f2u(v);
            bool eq = (u == prefix);
            bool gt = (u >  prefix);
            unsigned beq = __ballot_sync(~0u, eq);
            int tr = ties + __popc(beq & lmask);
            bool act = gt || (eq && tr < need);
            unsigned ba = __ballot_sync(~0u, act);
            if (act){
                int pos = base + __popc(ba & lmask);
                s_aidx[r*84 + pos] = c;
                s_aval[r*84 + pos] = v;
            }
            base += __popc(ba);
            ties += __popc(beq);
        }
    }
    __syncthreads();

    // ---- Stage 5: cue = sparse(dg) @ WmossyT  -> s_cueT[256][STR] ----
    for (int r = 0; r < 16; ++r){
        const int*   ai = s_aidx + r*84;
        const float* av = s_aval + r*84;
        float acc = 0.f;
        #pragma unroll 3
        for (int a = 0; a < KACT; ++a)
            acc = fmaf(av[a], g_WmossyT[ai[a]*NCA + tid], acc);
        s_cueT[tid*STR + r] = acc;
    }
    __syncthreads();

    // ---- Stage 6: 5-step recurrent tanh settle ----
    float cuev[16];
    #pragma unroll
    for (int r = 0; r < 16; ++r) cuev[r] = s_cueT[tid*STR + r];

    const float* cur = s_cueT;
    float* nxt = bufA;
    for (int it = 0; it < 5; ++it){
        float acc[16];
        #pragma unroll
        for (int r = 0; r < 16; ++r) acc[r] = 0.f;
        #pragma unroll 2
        for (int j = 0; j < NCA; ++j){
            float wv = g_WrecT[j*NCA + tid];
            fma16(acc, cur + j*STR, wv);
        }
        #pragma unroll
        for (int r = 0; r < 16; ++r)
            nxt[tid*STR + r] = tanhf(fmaf(0.7f, acc[r], 0.3f * cuev[r]));
        __syncthreads();
        cur = nxt;
        nxt = (cur == bufA) ? bufB : bufA;
    }
    // final state in bufA (writes: A,B,A,B,A)

    // ---- Stage 7: ca1_input (bufC), direct (bufD) ----
    {
        float acc[16];
        float bb = b_sc[tid];
        #pragma unroll
        for (int r = 0; r < 16; ++r) acc[r] = bb;
        #pragma unroll 2
        for (int j = 0; j < NCA; ++j){
            float wv = g_WscT[j*NCA + tid];
            fma16(acc, cur + j*STR, wv);
        }
        #pragma unroll
        for (int r = 0; r < 16; ++r) bufC[tid*STR + r] = acc[r];
    }
    {
        float acc[16];
        float bb = b_ta[tid];
        #pragma unroll
        for (int r = 0; r < 16; ++r) acc[r] = bb;
        #pragma unroll 4
        for (int k = 0; k < 64; ++k){
            float wv = g_WtaT[k*NCA + tid];
            fma16(acc, s_ecT + k*16, wv);
        }
        #pragma unroll
        for (int r = 0; r < 16; ++r) bufD[tid*STR + r] = acc[r];
    }
    __syncthreads();

    // ---- Stage 8: s_proj (bufA) = ca1 @ WcsT ; d_proj (bufB) = direct @ WcdT ----
    {
        float acc[16];
        #pragma unroll
        for (int r = 0; r < 16; ++r) acc[r] = 0.f;
        #pragma unroll 2
        for (int j = 0; j < NCA; ++j){
            float wv = g_WcsT[j*NCA + tid];
            fma16(acc, bufC + j*STR, wv);
        }
        #pragma unroll
        for (int r = 0; r < 16; ++r) bufA[tid*STR + r] = acc[r];
    }
    {
        float acc[16];
        #pragma unroll
        for (int r = 0; r < 16; ++r) acc[r] = 0.f;
        #pragma unroll 2
        for (int j = 0; j < NCA; ++j){
            float wv = g_WcdT[j*NCA + tid];
            fma16(acc, bufD + j*STR, wv);
        }
        #pragma unroll
        for (int r = 0; r < 16; ++r) bufB[tid*STR + r] = acc[r];
    }
    __syncthreads();

    // ---- Stage 9: cosine novelty (warp handles 2 rows) ----
    for (int rr = 0; rr < 2; ++rr){
        int r = w * 2 + rr;
        float sd = 0.f, sn = 0.f, dn = 0.f;
        for (int i = lane; i < NCA; i += 32){
            float sp = bufA[i*STR + r];
            float dp = bufB[i*STR + r];
            sd += sp*dp; sn += sp*sp; dn += dp*dp;
        }
        #pragma unroll
        for (int o = 16; o; o >>= 1){
            sd += __shfl_xor_sync(~0u, sd, o);
            sn += __shfl_xor_sync(~0u, sn, o);
            dn += __shfl_xor_sync(~0u, dn, o);
        }
        if (lane == 0){
            float s_n = fmaxf(sqrtf(sn), 1e-8f);
            float d_n = fmaxf(sqrtf(dn), 1e-8f);
            float cosv = sd / (s_n * d_n);
            float nov = fminf(fmaxf(1.f - cosv, 0.f), 1.f);
            s_nov[r] = nov;
            out[(long long)NB * NCA + row0 + r] = nov;
        }
    }
    __syncthreads();

    // ---- Stage 10: combined = g*direct + (1-g)*ca1 (into s_cueT), then tanh(comb @ WogT + b_og) ----
    #pragma unroll
    for (int r = 0; r < 16; ++r){
        float gte = s_nov[r];
        s_cueT[tid*STR + r] = fmaf(gte, bufD[tid*STR + r], (1.f - gte) * bufC[tid*STR + r]);
    }
    __syncthreads();
    {
        float acc[16];
        float bb = b_og[tid];
        #pragma unroll
        for (int r = 0; r < 16; ++r) acc[r] = bb;
        #pragma unroll 2
        for (int j = 0; j < NCA; ++j){
            float wv = g_WogT[j*NCA + tid];
            fma16(acc, s_cueT + j*STR, wv);
        }
        #pragma unroll
        for (int r = 0; r < 16; ++r)
            out[(long long)(row0 + r) * NCA + tid] = tanhf(acc[r]);
    }
}

// ---------------- launch ----------------
extern "C" void kernel_launch(void* const* d_in, const int* in_sizes, int n_in,
                              void* d_out, int out_size)
{
    const float* coords = (const float*)d_in[0];
    const float* ec_g   = (const float*)d_in[1];
    const float* ec_b   = (const float*)d_in[2];
    const float* W_pp   = (const float*)d_in[3];
    const float* b_pp   = (const float*)d_in[4];
    const float* dg_g   = (const float*)d_in[5];
    const float* dg_b   = (const float*)d_in[6];
    const float* W_mo   = (const float*)d_in[7];
    const float* W_rec  = (const float*)d_in[8];
    const float* W_sc   = (const float*)d_in[9];
    const float* b_sc   = (const float*)d_in[10];
    const float* W_ta   = (const float*)d_in[11];
    const float* b_ta   = (const float*)d_in[12];
    const float* W_cs   = (const float*)d_in[13];
    const float* W_cd   = (const float*)d_in[14];
    const float* W_og   = (const float*)d_in[15];
    const float* b_og   = (const float*)d_in[16];
    float* out = (float*)d_out;

    const size_t smem = (32768 + 1024 + 5120) * 4 + 8*256*4 + 16*84*4 + 16*84*4 + 16*4;
    cudaFuncSetAttribute(fused_kernel, cudaFuncAttributeMaxDynamicSharedMemorySize, (int)smem);

    colsum_kernel<<<256, 256>>>(coords);
    bufred_kernel<<<1, 64>>>();

    dim3 tb(32, 8);
    transpose_sel<<<dim3(64/32,  2048/32), tb>>>(W_pp, 2048, 64,  0);
    transpose_sel<<<dim3(2048/32, 256/32), tb>>>(W_mo, 256, 2048, 1);
    transpose_sel<<<dim3(8, 8), tb>>>(W_rec, 256, 256, 2);
    transpose_sel<<<dim3(8, 8), tb>>>(W_sc,  256, 256, 3);
    transpose_sel<<<dim3(8, 8), tb>>>(W_cs,  256, 256, 4);
    transpose_sel<<<dim3(8, 8), tb>>>(W_cd,  256, 256, 5);
    transpose_sel<<<dim3(8, 8), tb>>>(W_og,  256, 256, 6);
    transpose_sel<<<dim3(64/32, 256/32), tb>>>(W_ta, 256, 64, 7);

    fused_kernel<<<NB / MR, NTHR, smem>>>(coords, ec_g, ec_b, b_pp, dg_g, dg_b,
                                          b_sc, b_ta, b_og, out);
}

// round 2
// speedup vs baseline: 2.0366x; 2.0366x over previous
#include <cuda_runtime.h>

#define NB   32768
#define NCO  64
#define NDG  2048
#define NCA  256
#define KACT 81
#define MR   16
#define NTHR 256
#define STR  20   // padded stride (float4-aligned) for [256][16] transposed tiles

// ---------------- device-global scratch ----------------
__device__ float4 g_Wpp4[16 * NDG];      // [k4][c]  k4=0..15, c=0..2047
__device__ float  g_WmossyT[NDG * NCA];  // [d][c]
__device__ float4 g_Wrec4[64 * NCA];     // [j4][c]
__device__ float4 g_Wsc4 [64 * NCA];
__device__ float4 g_Wcs4 [64 * NCA];
__device__ float4 g_Wcd4 [64 * NCA];
__device__ float4 g_Wog4 [64 * NCA];
__device__ float4 g_Wta4 [16 * NCA];     // [k4][c]
__device__ float  g_part[256 * NCO];

// order-preserving float->uint key
__device__ __forceinline__ unsigned f2u(float f){
    unsigned u = __float_as_uint(f);
    return u ^ ((u & 0x80000000u) ? 0xFFFFFFFFu : 0x80000000u);
}

__device__ __forceinline__ void fma16(float acc[16], const float* __restrict__ sT, float wv){
    const float4* e = (const float4*)sT;
    float4 a=e[0], b=e[1], c=e[2], d=e[3];
    acc[0]=fmaf(a.x,wv,acc[0]);  acc[1]=fmaf(a.y,wv,acc[1]);  acc[2]=fmaf(a.z,wv,acc[2]);  acc[3]=fmaf(a.w,wv,acc[3]);
    acc[4]=fmaf(b.x,wv,acc[4]);  acc[5]=fmaf(b.y,wv,acc[5]);  acc[6]=fmaf(b.z,wv,acc[6]);  acc[7]=fmaf(b.w,wv,acc[7]);
    acc[8]=fmaf(c.x,wv,acc[8]);  acc[9]=fmaf(c.y,wv,acc[9]);  acc[10]=fmaf(c.z,wv,acc[10]); acc[11]=fmaf(c.w,wv,acc[11]);
    acc[12]=fmaf(d.x,wv,acc[12]); acc[13]=fmaf(d.y,wv,acc[13]); acc[14]=fmaf(d.z,wv,acc[14]); acc[15]=fmaf(d.w,wv,acc[15]);
}

// one GEMV-16 over 256 inputs with float4-interleaved weights
__device__ __forceinline__ void gemv256(float acc[16], const float* __restrict__ src,
                                        const float4* __restrict__ w4, int tid){
    #pragma unroll 4
    for (int j4 = 0; j4 < 64; ++j4){
        float4 wv = w4[j4 * NCA + tid];
        fma16(acc, src + (4*j4+0)*STR, wv.x);
        fma16(acc, src + (4*j4+1)*STR, wv.y);
        fma16(acc, src + (4*j4+2)*STR, wv.z);
        fma16(acc, src + (4*j4+3)*STR, wv.w);
    }
}

// ---------------- single prep kernel: all weight re-layouts + column partial sums ----------------
__global__ void prep_kernel(const float* __restrict__ coords,
                            const float* __restrict__ W_pp, const float* __restrict__ W_mo,
                            const float* __restrict__ W_rec, const float* __restrict__ W_sc,
                            const float* __restrict__ W_cs,  const float* __restrict__ W_cd,
                            const float* __restrict__ W_og,  const float* __restrict__ W_ta)
{
    __shared__ float s[4][64];
    const int b = blockIdx.x, tid = threadIdx.x;

    if (b < 256){
        // column partial sums of coords: 128 rows per block
        int c = tid & 63, g = tid >> 6;
        int r0 = b * 128 + g * 32;
        float acc = 0.f;
        #pragma unroll 8
        for (int i = 0; i < 32; ++i) acc += coords[(r0 + i) * 64 + c];
        s[g][c] = acc;
        __syncthreads();
        if (g == 0) g_part[b * 64 + c] = s[0][c] + s[1][c] + s[2][c] + s[3][c];
    } else if (b < 384){
        // W_pp [2048][64] -> g_Wpp4[k4*2048 + c]
        int e = (b - 256) * 256 + tid;          // 0..32767
        int c = e >> 4, k4 = e & 15;
        g_Wpp4[k4 * NDG + c] = *(const float4*)(W_pp + c * 64 + 4 * k4);
    } else if (b < 2432){
        // W_mossy [256][2048] -> g_WmossyT[d*256 + c]
        int e = (b - 384) * 256 + tid;          // 0..524287
        int c = e >> 11, d = e & 2047;
        g_WmossyT[d * NCA + c] = W_mo[e];
    } else if (b < 2752){
        // 5 square [256][256] weights -> float4-interleaved [j4*256 + c]
        int t = (b - 2432) >> 6;
        int e = ((b - 2432) & 63) * 256 + tid;  // 0..16383
        int c = e >> 6, j4 = e & 63;
        const float* src = (t==0)?W_rec:(t==1)?W_sc:(t==2)?W_cs:(t==3)?W_cd:W_og;
        float4* dst = (t==0)?g_Wrec4:(t==1)?g_Wsc4:(t==2)?g_Wcs4:(t==3)?g_Wcd4:g_Wog4;
        dst[j4 * NCA + c] = *(const float4*)(src + c * 256 + 4 * j4);
    } else {
        // W_ta [256][64] -> g_Wta4[k4*256 + c]
        int e = (b - 2752) * 256 + tid;         // 0..4095
        int c = e >> 4, k4 = e & 15;
        g_Wta4[k4 * NCA + c] = *(const float4*)(W_ta + c * 64 + 4 * k4);
    }
}

// ---------------- fused pipeline: 16 rows per block ----------------
extern "C" __global__ void __launch_bounds__(NTHR, 1)
fused_kernel(const float* __restrict__ coords,
             const float* __restrict__ ec_g,  const float* __restrict__ ec_b,
             const float* __restrict__ b_pp,
             const float* __restrict__ dg_g,  const float* __restrict__ dg_b,
             const float* __restrict__ b_sc,  const float* __restrict__ b_ta,
             const float* __restrict__ b_og,
             float* __restrict__ out)
{
    extern __shared__ float sm[];
    float*    pool     = sm;                          // 32768 f
    float*    s_ecT    = sm + 32768;                  // 1024 f : [64][16]
    float*    s_cueT   = s_ecT + 1024;                // 5120 f : [256][STR]
    float2*   s_act    = (float2*)(s_cueT + 5120);    // 16 x 84 float2 (val, off)
    unsigned* s_hist   = (unsigned*)(s_act + MR*84);  // 8 x 256
    float*    s_tmp    = (float*)(s_hist + 8*256);    // 256
    float*    s_bufadd = s_tmp + 256;                 // 64
    float*    s_nov    = s_bufadd + 64;               // 16

    float* bufA = pool;
    float* bufB = pool + 5120;
    float* bufC = pool + 10240;
    float* bufD = pool + 15360;

    const int tid  = threadIdx.x;
    const int w    = tid >> 5;
    const int lane = tid & 31;
    const unsigned lmask = (1u << lane) - 1u;
    const int row0 = blockIdx.x * MR;

    // ---- Stage 0: reduce column partials -> s_bufadd (0.05 * column mean) ----
    {
        int c = tid & 63, q = tid >> 6;
        float a = 0.f;
        #pragma unroll 8
        for (int i = 0; i < 64; ++i) a += g_part[(q * 64 + i) * 64 + c];
        s_tmp[q * 64 + c] = a;
        __syncthreads();
        if (tid < 64)
            s_bufadd[tid] = (0.05f / (float)NB) *
                (s_tmp[tid] + s_tmp[64 + tid] + s_tmp[128 + tid] + s_tmp[192 + tid]);
        __syncthreads();
    }

    // ---- Stage 1: EC layernorm (warp handles 2 rows) ----
    for (int rr = 0; rr < 2; ++rr){
        int r  = w * 2 + rr;
        int gr = row0 + r;
        float v1 = coords[gr*64 + lane]      + s_bufadd[lane];
        float v2 = coords[gr*64 + lane + 32] + s_bufadd[lane + 32];
        float s = v1 + v2, s2 = v1*v1 + v2*v2;
        #pragma unroll
        for (int o = 16; o; o >>= 1){ s += __shfl_xor_sync(~0u, s, o); s2 += __shfl_xor_sync(~0u, s2, o); }
        float mu = s * (1.f/64.f);
        float rs = rsqrtf(s2 * (1.f/64.f) - mu*mu + 1e-5f);
        s_ecT[lane*16 + r]      = (v1 - mu) * rs * ec_g[lane]      + ec_b[lane];
        s_ecT[(lane+32)*16 + r] = (v2 - mu) * rs * ec_g[lane + 32] + ec_b[lane + 32];
    }
    __syncthreads();

    // ---- Stage 2: proj = relu(ec @ WppT + b_pp) -> pool[16][2048] ----
    for (int nt = 0; nt < 8; ++nt){
        int c = nt * 256 + tid;
        float acc[16];
        float bp = b_pp[c];
        #pragma unroll
        for (int r = 0; r < 16; ++r) acc[r] = bp;
        #pragma unroll 4
        for (int k4 = 0; k4 < 16; ++k4){
            float4 wv = g_Wpp4[k4 * NDG + c];
            fma16(acc, s_ecT + (4*k4+0)*16, wv.x);
            fma16(acc, s_ecT + (4*k4+1)*16, wv.y);
            fma16(acc, s_ecT + (4*k4+2)*16, wv.z);
            fma16(acc, s_ecT + (4*k4+3)*16, wv.w);
        }
        #pragma unroll
        for (int r = 0; r < 16; ++r) pool[r*NDG + c] = fmaxf(acc[r], 0.f);
    }
    __syncthreads();

    // ---- Stage 3+4: DG layernorm + exact top-81 radix select + compaction (2 rows/warp) ----
    unsigned* hist = s_hist + w * 256;
    for (int rr = 0; rr < 2; ++rr){
        int r = w * 2 + rr;
        float* row = pool + r * NDG;
        float s = 0.f, s2 = 0.f;
        for (int i = lane; i < NDG; i += 32){ float v = row[i]; s += v; s2 += v*v; }
        #pragma unroll
        for (int o = 16; o; o >>= 1){ s += __shfl_xor_sync(~0u, s, o); s2 += __shfl_xor_sync(~0u, s2, o); }
        float mu = s * (1.f/2048.f);
        float rs = rsqrtf(s2 * (1.f/2048.f) - mu*mu + 1e-5f);
        for (int i = lane; i < NDG; i += 32)
            row[i] = (row[i] - mu) * rs * dg_g[i] + dg_b[i];
        __syncwarp();

        // exact K-th largest via byte radix select on order-preserving key
        unsigned prefix = 0; int need = KACT;
        for (int p = 3; p >= 0; --p){
            for (int b = lane; b < 256; b += 32) hist[b] = 0;
            __syncwarp();
            unsigned himask = (p == 3) ? 0u : (0xFFFFFFFFu << ((p + 1) * 8));
            for (int i = lane; i < NDG; i += 32){
                unsigned u = f2u(row[i]);
                if ((u & himask) == prefix) atomicAdd(&hist[(u >> (p*8)) & 255], 1u);
            }
            __syncwarp();
            int b0 = 255 - lane * 8;
            unsigned cs[8]; unsigned cnt = 0;
            #pragma unroll
            for (int t = 0; t < 8; ++t){ cs[t] = hist[b0 - t]; cnt += cs[t]; }
            unsigned inc = cnt;
            #pragma unroll
            for (int o = 1; o < 32; o <<= 1){ unsigned v = __shfl_up_sync(~0u, inc, o); if (lane >= o) inc += v; }
            unsigned excl = inc - cnt;
            bool hit = (excl < (unsigned)need) && ((unsigned)need <= inc);
            unsigned bal = __ballot_sync(~0u, hit);
            int srcl = __ffs(bal) - 1;
            int selbin = 0, newneed = 0, found = 0;
            if (hit){
                unsigned cum = excl;
                #pragma unroll
                for (int t = 0; t < 8; ++t){
                    unsigned nc = cum + cs[t];
                    if (!found && nc >= (unsigned)need){ selbin = b0 - t; newneed = need - (int)cum; found = 1; }
                    cum = nc;
                }
            }
            selbin = __shfl_sync(~0u, selbin, srcl);
            need   = __shfl_sync(~0u, newneed, srcl);
            prefix |= ((unsigned)selbin) << (p * 8);
        }

        // compact actives (keys > T, plus first `need` == T in ascending index order)
        int base = 0, ties = 0;
        for (int g = 0; g < 64; ++g){
            int c = g * 32 + lane;
            float v = row[c];
            unsigned u = f2u(v);
            bool eq = (u == prefix);
            bool gt = (u >  prefix);
            unsigned beq = __ballot_sync(~0u, eq);
            int tr = ties + __popc(beq & lmask);
            bool act = gt || (eq && tr < need);
            unsigned ba = __ballot_sync(~0u, act);
            if (act){
                int pos = base + __popc(ba & lmask);
                s_act[r*84 + pos] = make_float2(v, __int_as_float(c << 8));  // off = c*256
            }
            base += __popc(ba);
            ties += __popc(beq);
        }
    }
    __syncthreads();

    // ---- Stage 5: cue = sparse(dg) @ WmossyT  (a-outer, r-inner: 16 LDGs in flight) ----
    {
        float acc[16];
        #pragma unroll
        for (int r = 0; r < 16; ++r) acc[r] = 0.f;
        #pragma unroll 2
        for (int a = 0; a < KACT; ++a){
            #pragma unroll
            for (int r = 0; r < 16; ++r){
                float2 p = s_act[r*84 + a];
                acc[r] = fmaf(p.x, g_WmossyT[__float_as_int(p.y) + tid], acc[r]);
            }
        }
        #pragma unroll
        for (int r = 0; r < 16; ++r) s_cueT[tid*STR + r] = acc[r];
    }
    __syncthreads();

    // ---- Stage 6: 5-step recurrent tanh settle ----
    float cuev[16];
    #pragma unroll
    for (int r = 0; r < 16; ++r) cuev[r] = s_cueT[tid*STR + r];

    const float* cur = s_cueT;
    float* nxt = bufA;
    for (int it = 0; it < 5; ++it){
        float acc[16];
        #pragma unroll
        for (int r = 0; r < 16; ++r) acc[r] = 0.f;
        gemv256(acc, cur, g_Wrec4, tid);
        #pragma unroll
        for (int r = 0; r < 16; ++r)
            nxt[tid*STR + r] = tanhf(fmaf(0.7f, acc[r], 0.3f * cuev[r]));
        __syncthreads();
        cur = nxt;
        nxt = (cur == bufA) ? bufB : bufA;
    }
    // final state in bufA

    // ---- Stage 7: ca1_input (bufC), direct (bufD) ----
    {
        float acc[16];
        float bb = b_sc[tid];
        #pragma unroll
        for (int r = 0; r < 16; ++r) acc[r] = bb;
        gemv256(acc, cur, g_Wsc4, tid);
        #pragma unroll
        for (int r = 0; r < 16; ++r) bufC[tid*STR + r] = acc[r];
    }
    {
        float acc[16];
        float bb = b_ta[tid];
        #pragma unroll
        for (int r = 0; r < 16; ++r) acc[r] = bb;
        #pragma unroll 4
        for (int k4 = 0; k4 < 16; ++k4){
            float4 wv = g_Wta4[k4 * NCA + tid];
            fma16(acc, s_ecT + (4*k4+0)*16, wv.x);
            fma16(acc, s_ecT + (4*k4+1)*16, wv.y);
            fma16(acc, s_ecT + (4*k4+2)*16, wv.z);
            fma16(acc, s_ecT + (4*k4+3)*16, wv.w);
        }
        #pragma unroll
        for (int r = 0; r < 16; ++r) bufD[tid*STR + r] = acc[r];
    }
    __syncthreads();

    // ---- Stage 8: s_proj (bufA) = ca1 @ WcsT ; d_proj (bufB) = direct @ WcdT ----
    {
        float acc[16];
        #pragma unroll
        for (int r = 0; r < 16; ++r) acc[r] = 0.f;
        gemv256(acc, bufC, g_Wcs4, tid);
        #pragma unroll
        for (int r = 0; r < 16; ++r) bufA[tid*STR + r] = acc[r];
    }
    {
        float acc[16];
        #pragma unroll
        for (int r = 0; r < 16; ++r) acc[r] = 0.f;
        gemv256(acc, bufD, g_Wcd4, tid);
        #pragma unroll
        for (int r = 0; r < 16; ++r) bufB[tid*STR + r] = acc[r];
    }
    __syncthreads();

    // ---- Stage 9: cosine novelty (2 rows/warp) ----
    for (int rr = 0; rr < 2; ++rr){
        int r = w * 2 + rr;
        float sd = 0.f, sn = 0.f, dn = 0.f;
        for (int i = lane; i < NCA; i += 32){
            float sp = bufA[i*STR + r];
            float dp = bufB[i*STR + r];
            sd += sp*dp; sn += sp*sp; dn += dp*dp;
        }
        #pragma unroll
        for (int o = 16; o; o >>= 1){
            sd += __shfl_xor_sync(~0u, sd, o);
            sn += __shfl_xor_sync(~0u, sn, o);
            dn += __shfl_xor_sync(~0u, dn, o);
        }
        if (lane == 0){
            float s_n = fmaxf(sqrtf(sn), 1e-8f);
            float d_n = fmaxf(sqrtf(dn), 1e-8f);
            float cosv = sd / (s_n * d_n);
            float nov = fminf(fmaxf(1.f - cosv, 0.f), 1.f);
            s_nov[r] = nov;
            out[(long long)NB * NCA + row0 + r] = nov;
        }
    }
    __syncthreads();

    // ---- Stage 10: combined = g*direct + (1-g)*ca1 -> tanh(comb @ WogT + b_og) ----
    #pragma unroll
    for (int r = 0; r < 16; ++r){
        float gte = s_nov[r];
        s_cueT[tid*STR + r] = fmaf(gte, bufD[tid*STR + r], (1.f - gte) * bufC[tid*STR + r]);
    }
    __syncthreads();
    {
        float acc[16];
        float bb = b_og[tid];
        #pragma unroll
        for (int r = 0; r < 16; ++r) acc[r] = bb;
        gemv256(acc, s_cueT, g_Wog4, tid);
        #pragma unroll
        for (int r = 0; r < 16; ++r)
            out[(long long)(row0 + r) * NCA + tid] = tanhf(acc[r]);
    }
}

// ---------------- launch ----------------
extern "C" void kernel_launch(void* const* d_in, const int* in_sizes, int n_in,
                              void* d_out, int out_size)
{
    const float* coords = (const float*)d_in[0];
    const float* ec_g   = (const float*)d_in[1];
    const float* ec_b   = (const float*)d_in[2];
    const float* W_pp   = (const float*)d_in[3];
    const float* b_pp   = (const float*)d_in[4];
    const float* dg_g   = (const float*)d_in[5];
    const float* dg_b   = (const float*)d_in[6];
    const float* W_mo   = (const float*)d_in[7];
    const float* W_rec  = (const float*)d_in[8];
    const float* W_sc   = (const float*)d_in[9];
    const float* b_sc   = (const float*)d_in[10];
    const float* W_ta   = (const float*)d_in[11];
    const float* b_ta   = (const float*)d_in[12];
    const float* W_cs   = (const float*)d_in[13];
    const float* W_cd   = (const float*)d_in[14];
    const float* W_og   = (const float*)d_in[15];
    const float* b_og   = (const float*)d_in[16];
    float* out = (float*)d_out;

    // smem: pool 32768 + ecT 1024 + cueT 5120 + act 2688 + hist 2048 + tmp 256 + bufadd 64 + nov 16
    const size_t smem = (size_t)(32768 + 1024 + 5120 + 16*84*2 + 8*256 + 256 + 64 + 16) * 4;
    static int configured = 0;
    if (!configured){
        cudaFuncSetAttribute(fused_kernel, cudaFuncAttributeMaxDynamicSharedMemorySize, (int)smem);
        configured = 1;
    }

    prep_kernel<<<2768, 256>>>(coords, W_pp, W_mo, W_rec, W_sc, W_cs, W_cd, W_og, W_ta);
    fused_kernel<<<NB / MR, NTHR, smem>>>(coords, ec_g, ec_b, b_pp, dg_g, dg_b,
                                          b_sc, b_ta, b_og, out);
}